// round 4
// baseline (speedup 1.0000x reference)
#include <cuda_runtime.h>
#include <math.h>

#define NMAX 50000
#define EMAX 800000

// ---------------- scratch (static device globals; no allocations) -------------
__device__ float g_XL1[NMAX * 128];
__device__ float g_XR1[NMAX * 128];
__device__ float g_H  [NMAX * 128];
__device__ float g_XL2[NMAX * 64];
__device__ float g_XR2[NMAX * 64];
__device__ float g_T  [NMAX * 128];
__device__ int   g_src[EMAX];
__device__ int   g_dst[EMAX];
__device__ int   g_csr[EMAX];
__device__ int   g_cnt[NMAX];
__device__ int   g_incl[NMAX];
__device__ int   g_rowptr[NMAX + 1];
__device__ int   g_cursor[NMAX + 2];
__device__ int   g_bsum[1024];
__device__ int   g_dummy[4];
__device__ int   g_is64;

// ---------------- edge_index dtype detection -----------------------------------
// Reference declares int64, but JAX with x64 disabled materializes int32.
// Valid node ids < NMAX; if data were int32, an int64 read packs two ids and
// is >= 2^32 with overwhelming probability across 64 samples.
__global__ void detect_kernel(const long long* __restrict__ ei, int E) {
    if (blockIdx.x | threadIdx.x) return;
    int ok = 1;
    int m = E < 64 ? E : 64;
    for (int i = 0; i < m; i++) {
        long long v = ei[i];
        if (v < 0 || v >= NMAX) { ok = 0; break; }
    }
    g_is64 = ok;
}

// ---------------- CSR construction --------------------------------------------
__global__ void zero_cnt_kernel(int n) {
    int g = blockIdx.x * blockDim.x + threadIdx.x;
    if (g < n) g_cnt[g] = 0;
}

__global__ void hist_kernel(const void* __restrict__ eiv, int E, int n) {
    int e = blockIdx.x * blockDim.x + threadIdx.x;
    if (e >= E) return;
    int s, d;
    if (g_is64) {
        const long long* ei = (const long long*)eiv;
        s = (int)ei[e];
        d = (int)ei[(size_t)E + e];
    } else {
        const int* ei = (const int*)eiv;
        s = ei[e];
        d = ei[E + e];
    }
    // defensive: skip malformed ids instead of corrupting memory
    if ((unsigned)s >= (unsigned)n || (unsigned)d >= (unsigned)n) { s = 0; d = 0; }
    g_src[e] = s;
    g_dst[e] = d;
    atomicAdd(&g_cnt[d], 1);
}

// per-block inclusive scan (blockDim = 1024); phase 0: cnt->incl,bsum
// phase 1: bsum->bsum (single block, in place), block sums to dummy
__global__ void scan1_kernel(int n, int phase) {
    __shared__ int sh[1024];
    const int* in = (phase == 0) ? g_cnt : g_bsum;
    int* incl     = (phase == 0) ? g_incl : g_bsum;
    int* bsum     = (phase == 0) ? g_bsum : g_dummy;
    int g = blockIdx.x * 1024 + threadIdx.x;
    int v = (g < n) ? in[g] : 0;
    sh[threadIdx.x] = v;
    __syncthreads();
    for (int off = 1; off < 1024; off <<= 1) {
        int t = (threadIdx.x >= off) ? sh[threadIdx.x - off] : 0;
        __syncthreads();
        sh[threadIdx.x] += t;
        __syncthreads();
    }
    if (g < n) incl[g] = sh[threadIdx.x];
    if (threadIdx.x == 1023) bsum[blockIdx.x] = sh[1023];
}

__global__ void scan3_kernel(int n) {
    int g = blockIdx.x * blockDim.x + threadIdx.x;
    if (g == 0) { g_rowptr[0] = 0; g_cursor[0] = 0; }
    if (g < n) {
        int b = g >> 10;
        int v = g_incl[g] + (b > 0 ? g_bsum[b - 1] : 0);
        g_rowptr[g + 1] = v;
        g_cursor[g + 1] = v;
    }
}

__global__ void scatter_kernel(int E) {
    int e = blockIdx.x * blockDim.x + threadIdx.x;
    if (e >= E) return;
    int d = g_dst[e];
    int pos = atomicAdd(&g_cursor[d], 1);
    g_csr[pos] = g_src[e];
}

// ---------------- SGEMM: out[N x M] = X[N x K] @ W[K x M] (+bias,relu) --------
// Static shared memory only (<=48KB): K tiled in chunks of 64.
// 256 threads; each thread computes 8 rows x (M/32) cols.
// xsel: 2 -> X = g_H, else X = Xp.
// osel: 0 g_XL1, 1 g_XR1, 3 g_XL2, 4 g_XR2, 5 g_T, else outp.
template <int K, int M, bool BIAS, bool RELU>
__global__ void gemm_kernel(const float* __restrict__ Xp, const float* __restrict__ W,
                            const float* __restrict__ bias, float* __restrict__ outp,
                            int n, int xsel, int osel) {
    __shared__ float Ws[64 * M];
    __shared__ float Xs[64 * 64];
    const float* X = (xsel == 2) ? g_H : Xp;
    float* out;
    switch (osel) {
        case 0: out = g_XL1; break;
        case 1: out = g_XR1; break;
        case 3: out = g_XL2; break;
        case 4: out = g_XR2; break;
        case 5: out = g_T;   break;
        default: out = outp; break;
    }
    constexpr int TN = M / 32;
    int tid  = threadIdx.x;
    int lane = tid & 31;
    int rg   = tid >> 5;                  // 0..7
    int row0 = blockIdx.x * 64;

    float acc[8][TN];
#pragma unroll
    for (int i = 0; i < 8; i++)
#pragma unroll
        for (int j = 0; j < TN; j++) acc[i][j] = 0.f;

    for (int k0 = 0; k0 < K; k0 += 64) {
        if (k0) __syncthreads();
        for (int i = tid; i < 64 * M; i += 256) {
            int kk = i / M, mm = i - kk * M;
            Ws[i] = W[(size_t)(k0 + kk) * M + mm];
        }
        for (int i = tid; i < 64 * 64; i += 256) {
            int r = i >> 6, k = i & 63;
            int row = row0 + r;
            Xs[i] = (row < n) ? X[(size_t)row * K + k0 + k] : 0.f;
        }
        __syncthreads();

#pragma unroll 4
        for (int k = 0; k < 64; k++) {
            float wv[TN];
            if constexpr (TN == 4) {
                float4 w4 = *(const float4*)&Ws[k * M + lane * 4];
                wv[0] = w4.x; wv[1] = w4.y; wv[2] = w4.z; wv[3] = w4.w;
            } else {
                float2 w2 = *(const float2*)&Ws[k * M + lane * 2];
                wv[0] = w2.x; wv[1] = w2.y;
            }
#pragma unroll
            for (int i = 0; i < 8; i++) {
                float xv = Xs[(rg * 8 + i) * 64 + k];
#pragma unroll
                for (int j = 0; j < TN; j++) acc[i][j] += xv * wv[j];
            }
        }
    }

    float bv[TN];
#pragma unroll
    for (int j = 0; j < TN; j++) bv[j] = BIAS ? bias[lane * TN + j] : 0.f;

#pragma unroll
    for (int i = 0; i < 8; i++) {
        int row = row0 + rg * 8 + i;
        if (row < n) {
#pragma unroll
            for (int j = 0; j < TN; j++) {
                float v = acc[i][j] + bv[j];
                if constexpr (RELU) v = fmaxf(v, 0.f);
                out[(size_t)row * M + lane * TN + j] = v;
            }
        }
    }
}

// ---------------- GATv2 aggregation: warp-per-node online softmax --------------
template <int V>
__device__ __forceinline__ void ldv(float* d, const float* p) {
    if constexpr (V == 4) {
        float4 a = *(const float4*)p;
        d[0] = a.x; d[1] = a.y; d[2] = a.z; d[3] = a.w;
    } else {
        float2 a = *(const float2*)p;
        d[0] = a.x; d[1] = a.y;
    }
}

// LAYER 1: XL=g_XL1, XR=g_XR1, out=g_H; LAYER 2: XL=g_XL2, XR=g_XR2, out=param
template <int H, int C, bool RELU, int LAYER>
__global__ void gat_agg_kernel(const float* __restrict__ att, const float* __restrict__ bias,
                               float* __restrict__ outp, int n) {
    constexpr int D   = H * C;     // 128 or 64
    constexpr int V   = D / 32;    // 4 or 2 channels per lane
    constexpr int LPH = C / V;     // lanes per head: 4 or 32
    const float* XL = (LAYER == 1) ? g_XL1 : g_XL2;
    const float* XR = (LAYER == 1) ? g_XR1 : g_XR2;
    float* out      = (LAYER == 1) ? g_H   : outp;

    int w    = (blockIdx.x * blockDim.x + threadIdx.x) >> 5;
    int lane = threadIdx.x & 31;
    if (w >= n) return;

    float vr[V], vi[V], av[V], acc[V];
    ldv<V>(vr, XR + (size_t)w * D + lane * V);
    ldv<V>(vi, XL + (size_t)w * D + lane * V);
    ldv<V>(av, att + lane * V);

    // self-loop edge (src = dst = w)
    float p = 0.f;
#pragma unroll
    for (int v = 0; v < V; v++) {
        float e = vi[v] + vr[v];
        e = e > 0.f ? e : 0.2f * e;
        p += e * av[v];
    }
#pragma unroll
    for (int off = 1; off < LPH; off <<= 1) p += __shfl_xor_sync(0xffffffffu, p, off);
    float m = p, s = 1.f;
#pragma unroll
    for (int v = 0; v < V; v++) acc[v] = vi[v];

    int beg = g_rowptr[w], end = g_rowptr[w + 1];
    for (int base = beg; base < end; base += 32) {
        int myidx = 0;
        if (base + lane < end) myidx = g_csr[base + lane];
        int cnt = min(32, end - base);
        for (int j = 0; j < cnt; j++) {
            int sidx = __shfl_sync(0xffffffffu, myidx, j);
            float xv[V];
            ldv<V>(xv, XL + (size_t)sidx * D + lane * V);
            float pl = 0.f;
#pragma unroll
            for (int v = 0; v < V; v++) {
                float e = xv[v] + vr[v];
                e = e > 0.f ? e : 0.2f * e;
                pl += e * av[v];
            }
#pragma unroll
            for (int off = 1; off < LPH; off <<= 1)
                pl += __shfl_xor_sync(0xffffffffu, pl, off);
            float mn = fmaxf(m, pl);
            float es = __expf(m - mn);
            float ep = __expf(pl - mn);
            s = s * es + ep;
#pragma unroll
            for (int v = 0; v < V; v++) acc[v] = acc[v] * es + ep * xv[v];
            m = mn;
        }
    }

    float inv = 1.f / (s + 1e-16f);
#pragma unroll
    for (int v = 0; v < V; v++) {
        float o = acc[v] * inv + bias[lane * V + v];
        if constexpr (RELU) o = fmaxf(o, 0.f);
        acc[v] = o;
    }
    float* op = out + (size_t)w * D + lane * V;
    if constexpr (V == 4) *(float4*)op = make_float4(acc[0], acc[1], acc[2], acc[3]);
    else                  *(float2*)op = make_float2(acc[0], acc[1]);
}

// ---------------- final tiny classifier layer: logits = g_T @ Wc2 + bc2 --------
__global__ void logits_kernel(const float* __restrict__ Wc2, const float* __restrict__ bc2,
                              float* __restrict__ lg, int n) {
    int w    = (blockIdx.x * blockDim.x + threadIdx.x) >> 5;
    int lane = threadIdx.x & 31;
    if (w >= n) return;
    float4 t = *(const float4*)&g_T[(size_t)w * 128 + lane * 4];
    int c = lane * 4;
    float l0 = t.x * Wc2[c * 2]         + t.y * Wc2[(c + 1) * 2]
             + t.z * Wc2[(c + 2) * 2]   + t.w * Wc2[(c + 3) * 2];
    float l1 = t.x * Wc2[c * 2 + 1]     + t.y * Wc2[(c + 1) * 2 + 1]
             + t.z * Wc2[(c + 2) * 2 + 1] + t.w * Wc2[(c + 3) * 2 + 1];
#pragma unroll
    for (int off = 16; off >= 1; off >>= 1) {
        l0 += __shfl_xor_sync(0xffffffffu, l0, off);
        l1 += __shfl_xor_sync(0xffffffffu, l1, off);
    }
    if (lane == 0) {
        lg[(size_t)w * 2 + 0] = l0 + bc2[0];
        lg[(size_t)w * 2 + 1] = l1 + bc2[1];
    }
}

// ---------------- launch --------------------------------------------------------
extern "C" void kernel_launch(void* const* d_in, const int* in_sizes, int n_in,
                              void* d_out, int out_size) {
    const float*     x    = (const float*)d_in[0];
    const void*      ei   = d_in[1];
    const float*     Wl1  = (const float*)d_in[3];
    const float*     Wr1  = (const float*)d_in[4];
    const float*     att1 = (const float*)d_in[5];
    const float*     b1   = (const float*)d_in[6];
    const float*     Wl2  = (const float*)d_in[7];
    const float*     Wr2  = (const float*)d_in[8];
    const float*     att2 = (const float*)d_in[9];
    const float*     b2   = (const float*)d_in[10];
    const float*     Wc1  = (const float*)d_in[15];
    const float*     bc1  = (const float*)d_in[16];
    const float*     Wc2  = (const float*)d_in[17];
    const float*     bc2  = (const float*)d_in[18];

    int N = in_sizes[0] / 128;
    int E = in_sizes[1] / 2;
    float* out = (float*)d_out;
    float* emb = out;                       // [N, 64]
    float* lg  = out + (size_t)N * 64;      // [N, 2]

    // ---- CSR build (shared by both GAT layers) ----
    detect_kernel<<<1, 32>>>((const long long*)ei, E);
    zero_cnt_kernel<<<(N + 255) / 256, 256>>>(N);
    hist_kernel<<<(E + 255) / 256, 256>>>(ei, E, N);
    int nblk = (N + 1023) / 1024;
    scan1_kernel<<<nblk, 1024>>>(N, 0);
    scan1_kernel<<<1, 1024>>>(nblk, 1);
    scan3_kernel<<<(N + 255) / 256, 256>>>(N);
    scatter_kernel<<<(E + 255) / 256, 256>>>(E);

    int gblk = (N + 63) / 64;
    int ablk = ((N * 32) + 255) / 256;

    // ---- layer 1 ----
    gemm_kernel<128, 128, false, false><<<gblk, 256>>>(x, Wl1, nullptr, nullptr, N, -1, 0);
    gemm_kernel<128, 128, false, false><<<gblk, 256>>>(x, Wr1, nullptr, nullptr, N, -1, 1);
    gat_agg_kernel<8, 16, true, 1><<<ablk, 256>>>(att1, b1, nullptr, N);

    // ---- layer 2 ----
    gemm_kernel<128, 64, false, false><<<gblk, 256>>>(nullptr, Wl2, nullptr, nullptr, N, 2, 3);
    gemm_kernel<128, 64, false, false><<<gblk, 256>>>(nullptr, Wr2, nullptr, nullptr, N, 2, 4);
    gat_agg_kernel<1, 64, false, 2><<<ablk, 256>>>(att2, b2, emb, N);

    // ---- classifier ----
    if (out_size >= N * 66) {
        gemm_kernel<64, 128, true, true><<<gblk, 256>>>(emb, Wc1, bc1, nullptr, N, -1, 5);
        logits_kernel<<<ablk, 256>>>(Wc2, bc2, lg, N);
    }
}